// round 5
// baseline (speedup 1.0000x reference)
#include <cuda_runtime.h>
#include <cuda_fp16.h>
#include <math.h>

#define NN 500000
#define T 256
#define RB 592   // reduction blocks per graph

// ---------------- static device scratch ----------------
// g_zf: deg(2NN) | s1(2NN) | s2(2NN) | normF(2NN) | ns(2NN float2)  = 12NN floats
// only first 6NN (deg,s1,s2) need zeroing
__device__ __align__(16) float g_zf[12UL * NN];
// q rows: q1 = rows [0,2NN) (written fully by k_h1), q2 = rows [2NN,4NN) (zeroed)
__device__ __align__(16) __half g_zh[32UL * NN];
__device__ __align__(16) __half g_h1[16UL * NN];   // 2NN rows of 8 halves
__device__ __align__(16) __half g_x2[16UL * NN];
__device__ double g_stats[2][32];

#define DEGF (g_zf)
#define S1F  (g_zf + 2UL * NN)
#define S2F  (g_zf + 4UL * NN)
#define NRMF (g_zf + 6UL * NN)
#define NSF  ((float2*)(g_zf + 8UL * NN))
#define Q1R  ((uint4*)g_zh)
#define Q2R  (((uint4*)g_zh) + 2UL * NN)
#define H1R  ((uint4*)g_h1)
#define X2R  ((uint4*)g_x2)

// ---------------- helpers ----------------
template <int K>
__device__ __forceinline__ void block_reduce_add(double* vals, double* out) {
    __shared__ double sm[K][33];
    int lane = threadIdx.x & 31, wid = threadIdx.x >> 5;
#pragma unroll
    for (int k = 0; k < K; k++) {
        double v = vals[k];
#pragma unroll
        for (int o = 16; o; o >>= 1) v += __shfl_down_sync(0xffffffffu, v, o);
        if (lane == 0) sm[k][wid] = v;
    }
    __syncthreads();
    int nw = blockDim.x >> 5;
    if (wid == 0) {
#pragma unroll
        for (int k = 0; k < K; k++) {
            double v = (lane < nw) ? sm[k][lane] : 0.0;
#pragma unroll
            for (int o = 16; o; o >>= 1) v += __shfl_down_sync(0xffffffffu, v, o);
            if (lane == 0) atomicAdd(&out[k], v);
        }
    }
}

__device__ __forceinline__ void red_add_v4h2(__half* addr, unsigned a, unsigned b, unsigned c, unsigned d) {
    asm volatile("red.global.add.noftz.v4.f16x2 [%0], {%1,%2,%3,%4};"
                 :: "l"(addr), "r"(a), "r"(b), "r"(c), "r"(d) : "memory");
}
__device__ __forceinline__ unsigned h2u(__half2 v) { return *reinterpret_cast<unsigned*>(&v); }

// compute layer-1 coefficients for graph g into cf[24] ({A,B,C} x 7, stride 8)
__device__ void coef1_compute(int g, const float* W_init, const float* b_init,
                              const float* Wg, const float* bg, const float* Wt1,
                              const float* g1, const float* b1, float* cf) {
    float xrow[4];
    for (int j = 0; j < 4; j++) {
        float s = b_init[j];
        for (int i = 0; i < 12; i++) s += W_init[i * 4 + j];
        xrow[j] = s;
    }
    float hrow[7];
    for (int k = 0; k < 7; k++) {
        float s = bg[k];
        for (int j = 0; j < 4; j++) s += xrow[j] * Wg[j * 7 + k];
        hrow[k] = 1.0f / (1.0f + expf(-s));
    }
    const double inv_n = 1.0 / (double)NN;
    double m1 = g_stats[g][0] * inv_n, m2 = g_stats[g][1] * inv_n;
    double v1 = g_stats[g][2] * inv_n - m1 * m1;
    double v2 = g_stats[g][3] * inv_n - m2 * m2;
    double c12 = g_stats[g][4] * inv_n - m1 * m2;
    for (int j = 0; j < 7; j++) {
        float a = 0.f, b = 0.f, c = 0.f;
        for (int k = 0; k < 7; k++) {
            a += hrow[k] * Wt1[k * 7 + j];
            b += hrow[k] * Wt1[(7 + k) * 7 + j];
            c += hrow[k] * Wt1[(14 + k) * 7 + j];
        }
        double mean = (double)a + m1 * (double)b + m2 * (double)c;
        double var = (double)b * b * v1 + (double)c * c * v2 + 2.0 * (double)b * c * c12;
        double sc = (double)g1[j] / sqrt(var + 1e-5);
        cf[j]      = (float)(((double)a - mean) * sc + (double)b1[j]);
        cf[8 + j]  = (float)((double)b * sc);
        cf[16 + j] = (float)((double)c * sc);
    }
}

// ---------------- kernels ----------------
__global__ void k_zero() {
    size_t tid = (size_t)blockIdx.x * blockDim.x + threadIdx.x;
    size_t stride = (size_t)gridDim.x * blockDim.x;
    const size_t n1 = 6UL * NN / 4;    // deg,s1,s2 float4s
    float4 z = make_float4(0.f, 0.f, 0.f, 0.f);
    for (size_t k = tid; k < n1; k += stride) ((float4*)g_zf)[k] = z;
    uint4* q2 = (uint4*)Q2R;
    for (size_t k = tid; k < 2UL * NN; k += stride) q2[k] = make_uint4(0, 0, 0, 0);
    if (tid < 64) ((double*)g_stats)[tid] = 0.0;
}

__global__ void k_deg(const int* __restrict__ d0, const int* __restrict__ d1,
                      int E0, int E1, int nb0) {
    int b = blockIdx.x, off = 0;
    const int* dst; int E;
    if (b < nb0) { dst = d0; E = E0; }
    else { b -= nb0; dst = d1; E = E1; off = NN; }
    int base = (b * blockDim.x + threadIdx.x) * 4;
    if (base + 3 < E) {
        int4 d = *(const int4*)(dst + base);
        atomicAdd(&DEGF[d.x + off], 1.f); atomicAdd(&DEGF[d.y + off], 1.f);
        atomicAdd(&DEGF[d.z + off], 1.f); atomicAdd(&DEGF[d.w + off], 1.f);
    } else {
        for (int e = base; e < E; e++) atomicAdd(&DEGF[dst[e] + off], 1.f);
    }
}

__global__ void k_norm() {
    int i = blockIdx.x * blockDim.x + threadIdx.x;
    if (i < 2 * NN) NRMF[i] = rsqrtf(fmaxf(DEGF[i], 1.0f));
}

__global__ void k_p1(const int* __restrict__ s0, const int* __restrict__ d0,
                     const int* __restrict__ s1, const int* __restrict__ d1,
                     int E0, int E1, int nb0) {
    int b = blockIdx.x, off = 0;
    const int *src, *dst; int E;
    if (b < nb0) { src = s0; dst = d0; E = E0; }
    else { b -= nb0; src = s1; dst = d1; E = E1; off = NN; }
    int base = (b * blockDim.x + threadIdx.x) * 4;
    if (base + 3 < E) {
        int4 s = *(const int4*)(src + base);
        int4 d = *(const int4*)(dst + base);
        float w0 = __ldg(&NRMF[s.x + off]);
        float w1 = __ldg(&NRMF[s.y + off]);
        float w2 = __ldg(&NRMF[s.z + off]);
        float w3 = __ldg(&NRMF[s.w + off]);
        atomicAdd(&S1F[d.x + off], w0);
        atomicAdd(&S1F[d.y + off], w1);
        atomicAdd(&S1F[d.z + off], w2);
        atomicAdd(&S1F[d.w + off], w3);
    } else {
        for (int e = base; e < E; e++)
            atomicAdd(&S1F[dst[e] + off], __ldg(&NRMF[src[e] + off]));
    }
}

__global__ void k_pack() {  // ns = {norm, s1} full 8B stores
    int i = blockIdx.x * blockDim.x + threadIdx.x;
    if (i < 2 * NN) NSF[i] = make_float2(NRMF[i], S1F[i]);
}

__global__ void k_p2(const int* __restrict__ s0, const int* __restrict__ d0,
                     const int* __restrict__ s1, const int* __restrict__ d1,
                     int E0, int E1, int nb0) {
    int b = blockIdx.x, off = 0;
    const int *src, *dst; int E;
    if (b < nb0) { src = s0; dst = d0; E = E0; }
    else { b -= nb0; src = s1; dst = d1; E = E1; off = NN; }
    int base = (b * blockDim.x + threadIdx.x) * 4;
    if (base + 3 < E) {
        int4 s = *(const int4*)(src + base);
        int4 d = *(const int4*)(dst + base);
        float2 a = __ldg(&NSF[s.x + off]);
        float2 bb = __ldg(&NSF[s.y + off]);
        float2 c = __ldg(&NSF[s.z + off]);
        float2 f = __ldg(&NSF[s.w + off]);
        atomicAdd(&S2F[d.x + off], a.x * a.x * a.y);
        atomicAdd(&S2F[d.y + off], bb.x * bb.x * bb.y);
        atomicAdd(&S2F[d.z + off], c.x * c.x * c.y);
        atomicAdd(&S2F[d.w + off], f.x * f.x * f.y);
    } else {
        for (int e = base; e < E; e++) {
            float2 v = __ldg(&NSF[src[e] + off]);
            atomicAdd(&S2F[dst[e] + off], v.x * v.x * v.y);
        }
    }
}

__global__ void k_stats1(int nb0) {
    int g = blockIdx.x < nb0 ? 0 : 1;
    int b = g ? blockIdx.x - nb0 : blockIdx.x;
    int off = g * NN;
    double acc[5] = {0, 0, 0, 0, 0};
    int stride = nb0 * blockDim.x;
    for (int i = b * blockDim.x + threadIdx.x; i < NN; i += stride) {
        float2 v = NSF[i + off];
        float p1 = v.x * v.y, p2 = v.x * S2F[i + off];
        acc[0] += p1; acc[1] += p2;
        acc[2] += (double)p1 * p1; acc[3] += (double)p2 * p2; acc[4] += (double)p1 * p2;
    }
    block_reduce_add<5>(acc, g_stats[g]);
}

// h1 rows (lane7 = norm), full Q1 rows (lane7 = norm^2); coef1 computed per block
__global__ void k_h1(const float* __restrict__ W_init, const float* __restrict__ b_init,
                     const float* __restrict__ Wg, const float* __restrict__ bg,
                     const float* __restrict__ Wt1, const float* __restrict__ g1,
                     const float* __restrict__ b1) {
    __shared__ float cf[2][24];
    if (threadIdx.x < 2)
        coef1_compute(threadIdx.x, W_init, b_init, Wg, bg, Wt1, g1, b1, cf[threadIdx.x]);
    __syncthreads();
    int i = blockIdx.x * blockDim.x + threadIdx.x;
    if (i >= 2 * NN) return;
    int g = i >= NN;
    float2 v = NSF[i];
    float p1 = v.x * v.y, p2 = v.x * S2F[i];
    const float* c = cf[g];
    float o[7];
#pragma unroll
    for (int j = 0; j < 7; j++)
        o[j] = fmaxf(c[j] + p1 * c[8 + j] + p2 * c[16 + j], 0.f);
    __half2 h01 = __floats2half2_rn(o[0], o[1]);
    __half2 h23 = __floats2half2_rn(o[2], o[3]);
    __half2 h45 = __floats2half2_rn(o[4], o[5]);
    __half2 h67 = __floats2half2_rn(o[6], v.x);   // lane7 = norm (prop-1 weight)
    H1R[i] = make_uint4(h2u(h01), h2u(h23), h2u(h45), h2u(h67));
    __half2 w2 = __floats2half2_rn(0.f, v.x * v.x);
    Q1R[i] = make_uint4(0u, 0u, 0u, h2u(w2));     // Q1 zero + lane7 = norm^2 (prop-2 weight)
}

// 1 edge/thread (R3-proven): one 16B gather, one immediate v4.f16x2 RED
template <int STEP>
__global__ void k_qscat(const int* __restrict__ s0, const int* __restrict__ d0,
                        const int* __restrict__ s1, const int* __restrict__ d1,
                        int E0, int E1, int nb0) {
    int b = blockIdx.x, off = 0;
    const int *src, *dst; int E;
    if (b < nb0) { src = s0; dst = d0; E = E0; }
    else { b -= nb0; src = s1; dst = d1; E = E1; off = NN; }
    const uint4* in = (STEP == 1) ? H1R : Q1R;
    uint4* out = (STEP == 1) ? Q1R : Q2R;
    int e = b * blockDim.x + threadIdx.x;
    if (e >= E) return;
    int s = src[e] + off, d = dst[e] + off;
    uint4 r = __ldg(in + s);
    __half2 p01 = *(__half2*)&r.x, p23 = *(__half2*)&r.y;
    __half2 p45 = *(__half2*)&r.z, p67 = *(__half2*)&r.w;
    __half2 wv = __half2half2(__high2half(p67));
    unsigned v0 = h2u(__hmul2(p01, wv));
    unsigned v1 = h2u(__hmul2(p23, wv));
    unsigned v2 = h2u(__hmul2(p45, wv));
    unsigned v3 = h2u(__hmul2(p67, wv)) & 0x0000FFFFu;  // zero lane7
    red_add_v4h2((__half*)(out + d), v0, v1, v2, v3);
}

__global__ void k_passF(const float* __restrict__ Wt2, int nb0) {
    __shared__ float w[147];
    for (int k = threadIdx.x; k < 147; k += blockDim.x) w[k] = Wt2[k];
    __syncthreads();
    int g = blockIdx.x < nb0 ? 0 : 1;
    int b = g ? blockIdx.x - nb0 : blockIdx.x;
    int off = g * NN;
    double acc[14];
#pragma unroll
    for (int k = 0; k < 14; k++) acc[k] = 0.0;
    int stride = nb0 * blockDim.x;
    for (int i = b * blockDim.x + threadIdx.x; i < NN; i += stride) {
        float nn = NRMF[i + off];
        uint4 hr = H1R[i + off], ar = Q1R[i + off], br = Q2R[i + off];
        float v[21];
        {
            float2 t;
            t = __half22float2(*(__half2*)&hr.x); v[0] = t.x; v[1] = t.y;
            t = __half22float2(*(__half2*)&hr.y); v[2] = t.x; v[3] = t.y;
            t = __half22float2(*(__half2*)&hr.z); v[4] = t.x; v[5] = t.y;
            t = __half22float2(*(__half2*)&hr.w); v[6] = t.x;
            t = __half22float2(*(__half2*)&ar.x); v[7] = nn * t.x; v[8] = nn * t.y;
            t = __half22float2(*(__half2*)&ar.y); v[9] = nn * t.x; v[10] = nn * t.y;
            t = __half22float2(*(__half2*)&ar.z); v[11] = nn * t.x; v[12] = nn * t.y;
            t = __half22float2(*(__half2*)&ar.w); v[13] = nn * t.x;
            t = __half22float2(*(__half2*)&br.x); v[14] = nn * t.x; v[15] = nn * t.y;
            t = __half22float2(*(__half2*)&br.y); v[16] = nn * t.x; v[17] = nn * t.y;
            t = __half22float2(*(__half2*)&br.z); v[18] = nn * t.x; v[19] = nn * t.y;
            t = __half22float2(*(__half2*)&br.w); v[20] = nn * t.x;
        }
        float xr[7];
#pragma unroll
        for (int j = 0; j < 7; j++) {
            float s = 0.f;
#pragma unroll
            for (int k = 0; k < 21; k++) s += v[k] * w[k * 7 + j];
            xr[j] = s;
        }
        __half2 x01 = __floats2half2_rn(xr[0], xr[1]);
        __half2 x23 = __floats2half2_rn(xr[2], xr[3]);
        __half2 x45 = __floats2half2_rn(xr[4], xr[5]);
        __half2 x67 = __floats2half2_rn(xr[6], 0.f);
        X2R[i + off] = make_uint4(h2u(x01), h2u(x23), h2u(x45), h2u(x67));
#pragma unroll
        for (int j = 0; j < 7; j++) {
            acc[j] += xr[j];
            acc[7 + j] += (double)xr[j] * xr[j];
        }
    }
    block_reduce_add<14>(acc, g_stats[g] + 5);
}

__global__ void k_passG(const float* __restrict__ g2, const float* __restrict__ b2, int nb0) {
    __shared__ float sc[2][7], sh[2][7];
    if (threadIdx.x < 2) {
        int gg = threadIdx.x;
        const double inv_n = 1.0 / (double)NN;
        for (int j = 0; j < 7; j++) {
            double mean = g_stats[gg][5 + j] * inv_n;
            double var = g_stats[gg][12 + j] * inv_n - mean * mean;
            double s = (double)g2[j] / sqrt(var + 1e-5);
            sc[gg][j] = (float)s;
            sh[gg][j] = (float)((double)b2[j] - mean * s);
        }
    }
    __syncthreads();
    int g = blockIdx.x < nb0 ? 0 : 1;
    int b = g ? blockIdx.x - nb0 : blockIdx.x;
    int off = g * NN;
    double acc[7] = {0, 0, 0, 0, 0, 0, 0};
    int stride = nb0 * blockDim.x;
    for (int i = b * blockDim.x + threadIdx.x; i < NN; i += stride) {
        uint4 xr = X2R[i + off];
        float v[7];
        float2 t;
        t = __half22float2(*(__half2*)&xr.x); v[0] = t.x; v[1] = t.y;
        t = __half22float2(*(__half2*)&xr.y); v[2] = t.x; v[3] = t.y;
        t = __half22float2(*(__half2*)&xr.z); v[4] = t.x; v[5] = t.y;
        t = __half22float2(*(__half2*)&xr.w); v[6] = t.x;
#pragma unroll
        for (int j = 0; j < 7; j++)
            acc[j] += fmaxf(v[j] * sc[g][j] + sh[g][j], 0.f);
    }
    block_reduce_add<7>(acc, g_stats[g] + 19);
}

__global__ void k_fin(const float* __restrict__ Wd, const float* __restrict__ bd,
                      const float* __restrict__ Ws0, const float* __restrict__ bs0,
                      const float* __restrict__ Ws1, const float* __restrict__ bs1,
                      const float* __restrict__ Ws2, const float* __restrict__ bs2,
                      const float* __restrict__ Ws3, const float* __restrict__ bs3,
                      const float* __restrict__ Wsim, const float* __restrict__ bsim,
                      float* __restrict__ out) {
    if (threadIdx.x != 0) return;
    const double inv_n = 1.0 / (double)NN;
    float h[22];
    for (int g = 0; g < 2; g++)
        for (int m = 0; m < 11; m++) {
            double s = (double)bd[m];
            for (int j = 0; j < 7; j++)
                s += (g_stats[g][19 + j] * inv_n) * (double)Wd[j * 11 + m];
            h[g * 11 + m] = (float)s;
        }
    float t[7], u[7];
    for (int j = 0; j < 7; j++) {
        float s = bs0[j];
        for (int k = 0; k < 22; k++) s += h[k] * Ws0[k * 7 + j];
        t[j] = s;
    }
    for (int j = 0; j < 7; j++) {
        float s = bs1[j];
        for (int k = 0; k < 7; k++) s += t[k] * Ws1[k * 7 + j];
        u[j] = fmaxf(s, 0.f);
    }
    for (int j = 0; j < 7; j++) {
        float s = bs2[j];
        for (int k = 0; k < 7; k++) s += u[k] * Ws2[k * 7 + j];
        t[j] = fmaxf(s, 0.f);
    }
    for (int j = 0; j < 7; j++) {
        float s = bs3[j];
        for (int k = 0; k < 7; k++) s += t[k] * Ws3[k * 7 + j];
        u[j] = fmaxf(s, 0.f);
    }
    for (int m = 0; m < 12; m++) {
        float s = bsim[m];
        for (int j = 0; j < 7; j++) s += u[j] * Wsim[j * 12 + m];
        out[m] = 1.0f / (1.0f + expf(-s));
    }
}

// ---------------- launch ----------------
extern "C" void kernel_launch(void* const* d_in, const int* in_sizes, int n_in,
                              void* d_out, int out_size) {
    const int* src0 = (const int*)d_in[0];
    const int* dst0 = (const int*)d_in[1];
    const int* src1 = (const int*)d_in[2];
    const int* dst1 = (const int*)d_in[3];
    const float* W_init = (const float*)d_in[5];
    const float* b_init = (const float*)d_in[6];
    const float* Wg  = (const float*)d_in[7];
    const float* bg  = (const float*)d_in[8];
    const float* Wt1 = (const float*)d_in[9];
    const float* g1  = (const float*)d_in[10];
    const float* b1  = (const float*)d_in[11];
    const float* Wt2 = (const float*)d_in[12];
    const float* g2  = (const float*)d_in[13];
    const float* b2  = (const float*)d_in[14];
    const float* Wd  = (const float*)d_in[15];
    const float* bd  = (const float*)d_in[16];
    const float* Ws0 = (const float*)d_in[17];
    const float* bs0 = (const float*)d_in[18];
    const float* Ws1 = (const float*)d_in[19];
    const float* bs1 = (const float*)d_in[20];
    const float* Ws2 = (const float*)d_in[21];
    const float* bs2 = (const float*)d_in[22];
    const float* Ws3 = (const float*)d_in[23];
    const float* bs3 = (const float*)d_in[24];
    const float* Wsim = (const float*)d_in[25];
    const float* bsim = (const float*)d_in[26];

    const int E0 = in_sizes[0];
    const int E1 = in_sizes[2];
    const int eb0_4 = (E0 + T * 4 - 1) / (T * 4);
    const int eb1_4 = (E1 + T * 4 - 1) / (T * 4);
    const int eb4 = eb0_4 + eb1_4;
    const int eb0_1 = (E0 + T - 1) / T;
    const int eb1_1 = (E1 + T - 1) / T;
    const int eb1t = eb0_1 + eb1_1;
    const int nb = (2 * NN + T - 1) / T;

    k_zero<<<2368, T>>>();
    k_deg<<<eb4, T>>>(dst0, dst1, E0, E1, eb0_4);
    k_norm<<<nb, T>>>();
    k_p1<<<eb4, T>>>(src0, dst0, src1, dst1, E0, E1, eb0_4);
    k_pack<<<nb, T>>>();
    k_p2<<<eb4, T>>>(src0, dst0, src1, dst1, E0, E1, eb0_4);
    k_stats1<<<2 * RB, T>>>(RB);
    k_h1<<<nb, T>>>(W_init, b_init, Wg, bg, Wt1, g1, b1);
    k_qscat<1><<<eb1t, T>>>(src0, dst0, src1, dst1, E0, E1, eb0_1);
    k_qscat<2><<<eb1t, T>>>(src0, dst0, src1, dst1, E0, E1, eb0_1);
    k_passF<<<2 * RB, T>>>(Wt2, RB);
    k_passG<<<2 * RB, T>>>(g2, b2, RB);
    k_fin<<<1, 32>>>(Wd, bd, Ws0, bs0, Ws1, bs1, Ws2, bs2, Ws3, bs3, Wsim, bsim, (float*)d_out);
}

// round 6
// speedup vs baseline: 1.0849x; 1.0849x over previous
#include <cuda_runtime.h>
#include <cuda_fp16.h>
#include <math.h>

#define NN 500000
#define T 256
#define RB 592   // reduction blocks per graph

// ---------------- static device scratch ----------------
// g_zf: deg(2NN) | s1(2NN) | s2(2NN) | normF(2NN) | ns(2NN float2)  = 12NN floats
// only first 6NN (deg,s1,s2) need zeroing
__device__ __align__(16) float g_zf[12UL * NN];
// q rows: q1 = rows [0,2NN) (written fully by k_h1), q2 = rows [2NN,4NN) (zeroed)
__device__ __align__(16) __half g_zh[32UL * NN];
__device__ __align__(16) __half g_h1[16UL * NN];   // 2NN rows of 8 halves
__device__ __align__(16) __half g_x2[16UL * NN];
__device__ double g_stats[2][32];
__device__ float  g_coef[2][64];   // [0..7]A [8..15]B [16..23]C [24..31]bn2 scale [32..39]bn2 shift

#define DEGF (g_zf)
#define S1F  (g_zf + 2UL * NN)
#define S2F  (g_zf + 4UL * NN)
#define NRMF (g_zf + 6UL * NN)
#define NSF  ((float2*)(g_zf + 8UL * NN))
#define Q1R  ((uint4*)g_zh)
#define Q2R  (((uint4*)g_zh) + 2UL * NN)
#define H1R  ((uint4*)g_h1)
#define X2R  ((uint4*)g_x2)

// ---------------- helpers ----------------
template <int K>
__device__ __forceinline__ void block_reduce_add(double* vals, double* out) {
    __shared__ double sm[K][33];
    int lane = threadIdx.x & 31, wid = threadIdx.x >> 5;
#pragma unroll
    for (int k = 0; k < K; k++) {
        double v = vals[k];
#pragma unroll
        for (int o = 16; o; o >>= 1) v += __shfl_down_sync(0xffffffffu, v, o);
        if (lane == 0) sm[k][wid] = v;
    }
    __syncthreads();
    int nw = blockDim.x >> 5;
    if (wid == 0) {
#pragma unroll
        for (int k = 0; k < K; k++) {
            double v = (lane < nw) ? sm[k][lane] : 0.0;
#pragma unroll
            for (int o = 16; o; o >>= 1) v += __shfl_down_sync(0xffffffffu, v, o);
            if (lane == 0) atomicAdd(&out[k], v);
        }
    }
}

__device__ __forceinline__ void red_add_v4h2(__half* addr, unsigned a, unsigned b, unsigned c, unsigned d) {
    asm volatile("red.global.add.noftz.v4.f16x2 [%0], {%1,%2,%3,%4};"
                 :: "l"(addr), "r"(a), "r"(b), "r"(c), "r"(d) : "memory");
}
__device__ __forceinline__ unsigned h2u(__half2 v) { return *reinterpret_cast<unsigned*>(&v); }

// ---------------- kernels ----------------
__global__ void k_zero() {
    size_t tid = (size_t)blockIdx.x * blockDim.x + threadIdx.x;
    size_t stride = (size_t)gridDim.x * blockDim.x;
    const size_t n1 = 6UL * NN / 4;    // deg,s1,s2 float4s
    float4 z = make_float4(0.f, 0.f, 0.f, 0.f);
    for (size_t k = tid; k < n1; k += stride) ((float4*)g_zf)[k] = z;
    uint4* q2 = (uint4*)Q2R;
    for (size_t k = tid; k < 2UL * NN; k += stride) q2[k] = make_uint4(0, 0, 0, 0);
    if (tid < 64) ((double*)g_stats)[tid] = 0.0;
}

__global__ void k_deg(const int* __restrict__ d0, const int* __restrict__ d1,
                      int E0, int E1, int nb0) {
    int b = blockIdx.x, off = 0;
    const int* dst; int E;
    if (b < nb0) { dst = d0; E = E0; }
    else { b -= nb0; dst = d1; E = E1; off = NN; }
    int base = (b * blockDim.x + threadIdx.x) * 4;
    if (base + 3 < E) {
        int4 d = *(const int4*)(dst + base);
        atomicAdd(&DEGF[d.x + off], 1.f); atomicAdd(&DEGF[d.y + off], 1.f);
        atomicAdd(&DEGF[d.z + off], 1.f); atomicAdd(&DEGF[d.w + off], 1.f);
    } else {
        for (int e = base; e < E; e++) atomicAdd(&DEGF[dst[e] + off], 1.f);
    }
}

__global__ void k_norm() {
    int i = blockIdx.x * blockDim.x + threadIdx.x;
    if (i < 2 * NN) NRMF[i] = rsqrtf(fmaxf(DEGF[i], 1.0f));
}

__global__ void k_p1(const int* __restrict__ s0, const int* __restrict__ d0,
                     const int* __restrict__ s1, const int* __restrict__ d1,
                     int E0, int E1, int nb0) {
    int b = blockIdx.x, off = 0;
    const int *src, *dst; int E;
    if (b < nb0) { src = s0; dst = d0; E = E0; }
    else { b -= nb0; src = s1; dst = d1; E = E1; off = NN; }
    int base = (b * blockDim.x + threadIdx.x) * 4;
    if (base + 3 < E) {
        int4 s = *(const int4*)(src + base);
        int4 d = *(const int4*)(dst + base);
        float w0 = __ldg(&NRMF[s.x + off]);
        float w1 = __ldg(&NRMF[s.y + off]);
        float w2 = __ldg(&NRMF[s.z + off]);
        float w3 = __ldg(&NRMF[s.w + off]);
        atomicAdd(&S1F[d.x + off], w0);
        atomicAdd(&S1F[d.y + off], w1);
        atomicAdd(&S1F[d.z + off], w2);
        atomicAdd(&S1F[d.w + off], w3);
    } else {
        for (int e = base; e < E; e++)
            atomicAdd(&S1F[dst[e] + off], __ldg(&NRMF[src[e] + off]));
    }
}

__global__ void k_pack() {  // ns = {norm, s1} full 8B stores
    int i = blockIdx.x * blockDim.x + threadIdx.x;
    if (i < 2 * NN) NSF[i] = make_float2(NRMF[i], S1F[i]);
}

__global__ void k_p2(const int* __restrict__ s0, const int* __restrict__ d0,
                     const int* __restrict__ s1, const int* __restrict__ d1,
                     int E0, int E1, int nb0) {
    int b = blockIdx.x, off = 0;
    const int *src, *dst; int E;
    if (b < nb0) { src = s0; dst = d0; E = E0; }
    else { b -= nb0; src = s1; dst = d1; E = E1; off = NN; }
    int base = (b * blockDim.x + threadIdx.x) * 4;
    if (base + 3 < E) {
        int4 s = *(const int4*)(src + base);
        int4 d = *(const int4*)(dst + base);
        float2 a = __ldg(&NSF[s.x + off]);
        float2 bb = __ldg(&NSF[s.y + off]);
        float2 c = __ldg(&NSF[s.z + off]);
        float2 f = __ldg(&NSF[s.w + off]);
        atomicAdd(&S2F[d.x + off], a.x * a.x * a.y);
        atomicAdd(&S2F[d.y + off], bb.x * bb.x * bb.y);
        atomicAdd(&S2F[d.z + off], c.x * c.x * c.y);
        atomicAdd(&S2F[d.w + off], f.x * f.x * f.y);
    } else {
        for (int e = base; e < E; e++) {
            float2 v = __ldg(&NSF[src[e] + off]);
            atomicAdd(&S2F[dst[e] + off], v.x * v.x * v.y);
        }
    }
}

__global__ void k_stats1(int nb0) {
    int g = blockIdx.x < nb0 ? 0 : 1;
    int b = g ? blockIdx.x - nb0 : blockIdx.x;
    int off = g * NN;
    double acc[5] = {0, 0, 0, 0, 0};
    int stride = nb0 * blockDim.x;
    for (int i = b * blockDim.x + threadIdx.x; i < NN; i += stride) {
        float2 v = NSF[i + off];
        float p1 = v.x * v.y, p2 = v.x * S2F[i + off];
        acc[0] += p1; acc[1] += p2;
        acc[2] += (double)p1 * p1; acc[3] += (double)p2 * p2; acc[4] += (double)p1 * p2;
    }
    block_reduce_add<5>(acc, g_stats[g]);
}

// one tiny launch: fp64 coef math runs once per graph, not per block
__global__ void k_coef1(const float* __restrict__ W_init, const float* __restrict__ b_init,
                        const float* __restrict__ Wg, const float* __restrict__ bg,
                        const float* __restrict__ Wt1, const float* __restrict__ g1,
                        const float* __restrict__ b1) {
    int g = blockIdx.x;
    if (threadIdx.x != 0) return;
    float xrow[4];
    for (int j = 0; j < 4; j++) {
        float s = b_init[j];
        for (int i = 0; i < 12; i++) s += W_init[i * 4 + j];
        xrow[j] = s;
    }
    float hrow[7];
    for (int k = 0; k < 7; k++) {
        float s = bg[k];
        for (int j = 0; j < 4; j++) s += xrow[j] * Wg[j * 7 + k];
        hrow[k] = 1.0f / (1.0f + expf(-s));
    }
    const double inv_n = 1.0 / (double)NN;
    double m1 = g_stats[g][0] * inv_n, m2 = g_stats[g][1] * inv_n;
    double v1 = g_stats[g][2] * inv_n - m1 * m1;
    double v2 = g_stats[g][3] * inv_n - m2 * m2;
    double c12 = g_stats[g][4] * inv_n - m1 * m2;
    for (int j = 0; j < 7; j++) {
        float a = 0.f, b = 0.f, c = 0.f;
        for (int k = 0; k < 7; k++) {
            a += hrow[k] * Wt1[k * 7 + j];
            b += hrow[k] * Wt1[(7 + k) * 7 + j];
            c += hrow[k] * Wt1[(14 + k) * 7 + j];
        }
        double mean = (double)a + m1 * (double)b + m2 * (double)c;
        double var = (double)b * b * v1 + (double)c * c * v2 + 2.0 * (double)b * c * c12;
        double sc = (double)g1[j] / sqrt(var + 1e-5);
        g_coef[g][j]      = (float)(((double)a - mean) * sc + (double)b1[j]);
        g_coef[g][8 + j]  = (float)((double)b * sc);
        g_coef[g][16 + j] = (float)((double)c * sc);
    }
}

// h1 rows (lane7 = norm), full Q1 rows (lane7 = norm^2)
__global__ void k_h1() {
    __shared__ float cf[2][24];
    if (threadIdx.x < 48) {
        int g = threadIdx.x / 24, j = threadIdx.x % 24;
        cf[g][j] = g_coef[g][(j / 7) * 8 + (j % 7)];
    }
    __syncthreads();
    int i = blockIdx.x * blockDim.x + threadIdx.x;
    if (i >= 2 * NN) return;
    int g = i >= NN;
    float2 v = NSF[i];
    float p1 = v.x * v.y, p2 = v.x * S2F[i];
    const float* c = cf[g];
    float o[7];
#pragma unroll
    for (int j = 0; j < 7; j++)
        o[j] = fmaxf(c[j] + p1 * c[7 + j] + p2 * c[14 + j], 0.f);
    __half2 h01 = __floats2half2_rn(o[0], o[1]);
    __half2 h23 = __floats2half2_rn(o[2], o[3]);
    __half2 h45 = __floats2half2_rn(o[4], o[5]);
    __half2 h67 = __floats2half2_rn(o[6], v.x);   // lane7 = norm (prop-1 weight)
    H1R[i] = make_uint4(h2u(h01), h2u(h23), h2u(h45), h2u(h67));
    __half2 w2 = __floats2half2_rn(0.f, v.x * v.x);
    Q1R[i] = make_uint4(0u, 0u, 0u, h2u(w2));     // Q1 zero + lane7 = norm^2 (prop-2 weight)
}

// 1 edge/thread: one 16B gather, one immediate v4.f16x2 RED
template <int STEP>
__global__ void k_qscat(const int* __restrict__ s0, const int* __restrict__ d0,
                        const int* __restrict__ s1, const int* __restrict__ d1,
                        int E0, int E1, int nb0) {
    int b = blockIdx.x, off = 0;
    const int *src, *dst; int E;
    if (b < nb0) { src = s0; dst = d0; E = E0; }
    else { b -= nb0; src = s1; dst = d1; E = E1; off = NN; }
    const uint4* in = (STEP == 1) ? H1R : Q1R;
    uint4* out = (STEP == 1) ? Q1R : Q2R;
    int e = b * blockDim.x + threadIdx.x;
    if (e >= E) return;
    int s = src[e] + off, d = dst[e] + off;
    uint4 r = __ldg(in + s);
    __half2 p01 = *(__half2*)&r.x, p23 = *(__half2*)&r.y;
    __half2 p45 = *(__half2*)&r.z, p67 = *(__half2*)&r.w;
    __half2 wv = __half2half2(__high2half(p67));
    unsigned v0 = h2u(__hmul2(p01, wv));
    unsigned v1 = h2u(__hmul2(p23, wv));
    unsigned v2 = h2u(__hmul2(p45, wv));
    unsigned v3 = h2u(__hmul2(p67, wv)) & 0x0000FFFFu;  // zero lane7
    red_add_v4h2((__half*)(out + d), v0, v1, v2, v3);
}

__global__ void k_passF(const float* __restrict__ Wt2, int nb0) {
    __shared__ float w[147];
    for (int k = threadIdx.x; k < 147; k += blockDim.x) w[k] = Wt2[k];
    __syncthreads();
    int g = blockIdx.x < nb0 ? 0 : 1;
    int b = g ? blockIdx.x - nb0 : blockIdx.x;
    int off = g * NN;
    double acc[14];
#pragma unroll
    for (int k = 0; k < 14; k++) acc[k] = 0.0;
    int stride = nb0 * blockDim.x;
    for (int i = b * blockDim.x + threadIdx.x; i < NN; i += stride) {
        float nn = NRMF[i + off];
        uint4 hr = H1R[i + off], ar = Q1R[i + off], br = Q2R[i + off];
        float v[21];
        {
            float2 t;
            t = __half22float2(*(__half2*)&hr.x); v[0] = t.x; v[1] = t.y;
            t = __half22float2(*(__half2*)&hr.y); v[2] = t.x; v[3] = t.y;
            t = __half22float2(*(__half2*)&hr.z); v[4] = t.x; v[5] = t.y;
            t = __half22float2(*(__half2*)&hr.w); v[6] = t.x;
            t = __half22float2(*(__half2*)&ar.x); v[7] = nn * t.x; v[8] = nn * t.y;
            t = __half22float2(*(__half2*)&ar.y); v[9] = nn * t.x; v[10] = nn * t.y;
            t = __half22float2(*(__half2*)&ar.z); v[11] = nn * t.x; v[12] = nn * t.y;
            t = __half22float2(*(__half2*)&ar.w); v[13] = nn * t.x;
            t = __half22float2(*(__half2*)&br.x); v[14] = nn * t.x; v[15] = nn * t.y;
            t = __half22float2(*(__half2*)&br.y); v[16] = nn * t.x; v[17] = nn * t.y;
            t = __half22float2(*(__half2*)&br.z); v[18] = nn * t.x; v[19] = nn * t.y;
            t = __half22float2(*(__half2*)&br.w); v[20] = nn * t.x;
        }
        float xr[7];
#pragma unroll
        for (int j = 0; j < 7; j++) {
            float s = 0.f;
#pragma unroll
            for (int k = 0; k < 21; k++) s += v[k] * w[k * 7 + j];
            xr[j] = s;
        }
        __half2 x01 = __floats2half2_rn(xr[0], xr[1]);
        __half2 x23 = __floats2half2_rn(xr[2], xr[3]);
        __half2 x45 = __floats2half2_rn(xr[4], xr[5]);
        __half2 x67 = __floats2half2_rn(xr[6], 0.f);
        X2R[i + off] = make_uint4(h2u(x01), h2u(x23), h2u(x45), h2u(x67));
#pragma unroll
        for (int j = 0; j < 7; j++) {
            acc[j] += xr[j];
            acc[7 + j] += (double)xr[j] * xr[j];
        }
    }
    block_reduce_add<14>(acc, g_stats[g] + 5);
}

__global__ void k_coef2(const float* __restrict__ g2, const float* __restrict__ b2) {
    int g = blockIdx.x;
    if (threadIdx.x != 0) return;
    const double inv_n = 1.0 / (double)NN;
    for (int j = 0; j < 7; j++) {
        double mean = g_stats[g][5 + j] * inv_n;
        double var = g_stats[g][12 + j] * inv_n - mean * mean;
        double sc = (double)g2[j] / sqrt(var + 1e-5);
        g_coef[g][24 + j] = (float)sc;
        g_coef[g][32 + j] = (float)((double)b2[j] - mean * sc);
    }
}

__global__ void k_passG(int nb0) {
    __shared__ float sc[2][7], sh[2][7];
    if (threadIdx.x < 28) {
        int g = threadIdx.x / 14, j = threadIdx.x % 14;
        if (j < 7) sc[g][j] = g_coef[g][24 + j];
        else sh[g][j - 7] = g_coef[g][32 + j - 7];
    }
    __syncthreads();
    int g = blockIdx.x < nb0 ? 0 : 1;
    int b = g ? blockIdx.x - nb0 : blockIdx.x;
    int off = g * NN;
    double acc[7] = {0, 0, 0, 0, 0, 0, 0};
    int stride = nb0 * blockDim.x;
    for (int i = b * blockDim.x + threadIdx.x; i < NN; i += stride) {
        uint4 xr = X2R[i + off];
        float v[7];
        float2 t;
        t = __half22float2(*(__half2*)&xr.x); v[0] = t.x; v[1] = t.y;
        t = __half22float2(*(__half2*)&xr.y); v[2] = t.x; v[3] = t.y;
        t = __half22float2(*(__half2*)&xr.z); v[4] = t.x; v[5] = t.y;
        t = __half22float2(*(__half2*)&xr.w); v[6] = t.x;
#pragma unroll
        for (int j = 0; j < 7; j++)
            acc[j] += fmaxf(v[j] * sc[g][j] + sh[g][j], 0.f);
    }
    block_reduce_add<7>(acc, g_stats[g] + 19);
}

__global__ void k_fin(const float* __restrict__ Wd, const float* __restrict__ bd,
                      const float* __restrict__ Ws0, const float* __restrict__ bs0,
                      const float* __restrict__ Ws1, const float* __restrict__ bs1,
                      const float* __restrict__ Ws2, const float* __restrict__ bs2,
                      const float* __restrict__ Ws3, const float* __restrict__ bs3,
                      const float* __restrict__ Wsim, const float* __restrict__ bsim,
                      float* __restrict__ out) {
    if (threadIdx.x != 0) return;
    const double inv_n = 1.0 / (double)NN;
    float h[22];
    for (int g = 0; g < 2; g++)
        for (int m = 0; m < 11; m++) {
            double s = (double)bd[m];
            for (int j = 0; j < 7; j++)
                s += (g_stats[g][19 + j] * inv_n) * (double)Wd[j * 11 + m];
            h[g * 11 + m] = (float)s;
        }
    float t[7], u[7];
    for (int j = 0; j < 7; j++) {
        float s = bs0[j];
        for (int k = 0; k < 22; k++) s += h[k] * Ws0[k * 7 + j];
        t[j] = s;
    }
    for (int j = 0; j < 7; j++) {
        float s = bs1[j];
        for (int k = 0; k < 7; k++) s += t[k] * Ws1[k * 7 + j];
        u[j] = fmaxf(s, 0.f);
    }
    for (int j = 0; j < 7; j++) {
        float s = bs2[j];
        for (int k = 0; k < 7; k++) s += u[k] * Ws2[k * 7 + j];
        t[j] = fmaxf(s, 0.f);
    }
    for (int j = 0; j < 7; j++) {
        float s = bs3[j];
        for (int k = 0; k < 7; k++) s += t[k] * Ws3[k * 7 + j];
        u[j] = fmaxf(s, 0.f);
    }
    for (int m = 0; m < 12; m++) {
        float s = bsim[m];
        for (int j = 0; j < 7; j++) s += u[j] * Wsim[j * 12 + m];
        out[m] = 1.0f / (1.0f + expf(-s));
    }
}

// ---------------- launch ----------------
extern "C" void kernel_launch(void* const* d_in, const int* in_sizes, int n_in,
                              void* d_out, int out_size) {
    const int* src0 = (const int*)d_in[0];
    const int* dst0 = (const int*)d_in[1];
    const int* src1 = (const int*)d_in[2];
    const int* dst1 = (const int*)d_in[3];
    const float* W_init = (const float*)d_in[5];
    const float* b_init = (const float*)d_in[6];
    const float* Wg  = (const float*)d_in[7];
    const float* bg  = (const float*)d_in[8];
    const float* Wt1 = (const float*)d_in[9];
    const float* g1  = (const float*)d_in[10];
    const float* b1  = (const float*)d_in[11];
    const float* Wt2 = (const float*)d_in[12];
    const float* g2  = (const float*)d_in[13];
    const float* b2  = (const float*)d_in[14];
    const float* Wd  = (const float*)d_in[15];
    const float* bd  = (const float*)d_in[16];
    const float* Ws0 = (const float*)d_in[17];
    const float* bs0 = (const float*)d_in[18];
    const float* Ws1 = (const float*)d_in[19];
    const float* bs1 = (const float*)d_in[20];
    const float* Ws2 = (const float*)d_in[21];
    const float* bs2 = (const float*)d_in[22];
    const float* Ws3 = (const float*)d_in[23];
    const float* bs3 = (const float*)d_in[24];
    const float* Wsim = (const float*)d_in[25];
    const float* bsim = (const float*)d_in[26];

    const int E0 = in_sizes[0];
    const int E1 = in_sizes[2];
    const int eb0_4 = (E0 + T * 4 - 1) / (T * 4);
    const int eb1_4 = (E1 + T * 4 - 1) / (T * 4);
    const int eb4 = eb0_4 + eb1_4;
    const int eb0_1 = (E0 + T - 1) / T;
    const int eb1_1 = (E1 + T - 1) / T;
    const int eb1t = eb0_1 + eb1_1;
    const int nb = (2 * NN + T - 1) / T;

    k_zero<<<2368, T>>>();
    k_deg<<<eb4, T>>>(dst0, dst1, E0, E1, eb0_4);
    k_norm<<<nb, T>>>();
    k_p1<<<eb4, T>>>(src0, dst0, src1, dst1, E0, E1, eb0_4);
    k_pack<<<nb, T>>>();
    k_p2<<<eb4, T>>>(src0, dst0, src1, dst1, E0, E1, eb0_4);
    k_stats1<<<2 * RB, T>>>(RB);
    k_coef1<<<2, 32>>>(W_init, b_init, Wg, bg, Wt1, g1, b1);
    k_h1<<<nb, T>>>();
    k_qscat<1><<<eb1t, T>>>(src0, dst0, src1, dst1, E0, E1, eb0_1);
    k_qscat<2><<<eb1t, T>>>(src0, dst0, src1, dst1, E0, E1, eb0_1);
    k_passF<<<2 * RB, T>>>(Wt2, RB);
    k_coef2<<<2, 32>>>(g2, b2);
    k_passG<<<2 * RB, T>>>(RB);
    k_fin<<<1, 32>>>(Wd, bd, Ws0, bs0, Ws1, bs1, Ws2, bs2, Ws3, bs3, Wsim, bsim, (float*)d_out);
}